// round 10
// baseline (speedup 1.0000x reference)
#include <cuda_runtime.h>
#include <stdint.h>
#include <math.h>

#define BATCH  4
#define NHEADS 16
#define HEAD   64
#define SEQ    2048
#define EMBED  1024
#define QKVN   3072
#define NTOK   (BATCH * SEQ)   // 8192

// ---------------- scratch (device globals: allocation-free) ----------------
__device__ float g_q[BATCH * NHEADS * SEQ * HEAD];   // [B,H,S,D], tf32-rounded, Q pre-scaled
__device__ float g_k[BATCH * NHEADS * SEQ * HEAD];
__device__ float g_v[BATCH * NHEADS * SEQ * HEAD];
__device__ float g_attn[BATCH * SEQ * EMBED];        // [B,S,H*D], tf32-rounded
__device__ float g_xr[NTOK * EMBED];                 // X, tf32-rounded
__device__ float g_wqkv[QKVN * EMBED];               // packed [n][k], tf32-rounded
__device__ float g_wo[EMBED * EMBED];                // Wo [e][f], tf32-rounded

// ---------------- helpers ----------------
__device__ __forceinline__ float rnd32(float f) {
    uint32_t r;
    asm("cvt.rna.tf32.f32 %0, %1;" : "=r"(r) : "f"(f));
    return __uint_as_float(r);
}

__device__ __forceinline__ void mma8(float* c,
                                     uint32_t a0, uint32_t a1, uint32_t a2, uint32_t a3,
                                     uint32_t b0, uint32_t b1) {
    asm volatile(
        "mma.sync.aligned.m16n8k8.row.col.f32.tf32.tf32.f32 "
        "{%0,%1,%2,%3}, {%4,%5,%6,%7}, {%8,%9}, {%0,%1,%2,%3};"
        : "+f"(c[0]), "+f"(c[1]), "+f"(c[2]), "+f"(c[3])
        : "r"(a0), "r"(a1), "r"(a2), "r"(a3), "r"(b0), "r"(b1));
}

__device__ __forceinline__ void ldsm4(uint32_t* r, const void* p) {
    uint32_t a = (uint32_t)__cvta_generic_to_shared(p);
    asm volatile("ldmatrix.sync.aligned.m8n8.x4.shared.b16 {%0,%1,%2,%3}, [%4];"
                 : "=r"(r[0]), "=r"(r[1]), "=r"(r[2]), "=r"(r[3]) : "r"(a));
}

__device__ __forceinline__ void cp16(void* smem, const void* gmem) {
    uint32_t sa = (uint32_t)__cvta_generic_to_shared(smem);
    asm volatile("cp.async.cg.shared.global [%0], [%1], 16;" :: "r"(sa), "l"(gmem));
}
#define CP_COMMIT() asm volatile("cp.async.commit_group;")
#define CP_WAIT0()  asm volatile("cp.async.wait_group 0;")
#define CP_WAIT1()  asm volatile("cp.async.wait_group 1;")

// smem sizes (bytes)
#define GEMM_SMEM ((2 * 128 * 36 + 2 * 128 * 36) * 4)            // 73728
#define ATTN_SMEM ((3 * 32 * 68 + 3 * 32 * 72 + 128 * 36) * 4)   // 72192

// ============================================================================
// Prep kernels
// ============================================================================
__global__ __launch_bounds__(256) void round_x_kernel(const float* __restrict__ x) {
    int i = (blockIdx.x * 256 + threadIdx.x) * 4;
    float4 v = *(const float4*)(x + i);
    v.x = rnd32(v.x); v.y = rnd32(v.y); v.z = rnd32(v.z); v.w = rnd32(v.w);
    *(float4*)(g_xr + i) = v;
}

// g_wqkv[n][k]: n -> (mat, head, d)
__global__ __launch_bounds__(256) void pack_w_kernel(
    const float* __restrict__ Wq, const float* __restrict__ Wk, const float* __restrict__ Wv) {
    int i = blockIdx.x * 256 + threadIdx.x;      // over QKVN*EMBED
    int n = i >> 10;
    int k = i & 1023;
    int mat = n >> 10;
    int hn  = n & 1023;
    int h = hn >> 6, d = hn & 63;
    const float* w = (mat == 0) ? Wq : ((mat == 1) ? Wk : Wv);
    g_wqkv[i] = rnd32(w[((size_t)h * EMBED + k) * HEAD + d]);
}

__global__ __launch_bounds__(256) void round_wo_kernel(const float* __restrict__ Wo) {
    int i = (blockIdx.x * 256 + threadIdx.x) * 4;
    float4 v = *(const float4*)(Wo + i);
    v.x = rnd32(v.x); v.y = rnd32(v.y); v.z = rnd32(v.z); v.w = rnd32(v.w);
    *(float4*)(g_wo + i) = v;
}

// ============================================================================
// GEMM body: C[128x128] = A[128xK] * B^T (B stored [n][k], k-contiguous).
// K-chunk 32, 2-stage double buffer.  8 warps = 4(M) x 2(N); warp tile 32x64.
// Fragment loads via ldmatrix.x4 (24 LDSM vs 96 LDS per K32 per warp).
// ============================================================================
struct GemmAcc { float c[2][8][4]; };

__device__ __forceinline__ void gemm128_body(
    GemmAcc& acc,
    const float* __restrict__ aBase,   // A origin (row m0, col 0), row stride lda
    const float* __restrict__ bBase,   // B origin (row n0, col 0), row stride ldb
    int lda, int ldb)
{
    extern __shared__ float smem[];
    float (*As)[128][36] = (float(*)[128][36])smem;                  // [st][m][k]
    float (*Bs)[128][36] = (float(*)[128][36])(smem + 2 * 128 * 36); // [st][n][k]

    const int tid  = threadIdx.x;
    const int lane = tid & 31;
    const int warp = tid >> 5;
    const int wm   = warp & 3;         // M: 4 warps x 32 rows
    const int wn   = warp >> 2;        // N: 2 warps x 64 cols
    const int lmat = lane >> 3;        // 0..3
    const int lrow = lane & 7;

    // staging: 4 chunks/thread each for A and B (128 rows x 32 k = 1024 chunks)
    int sr[4], scol[4];
    const float* agp[4];
    const float* bgp[4];
    #pragma unroll
    for (int j = 0; j < 4; j++) {
        int chunk = tid + j * 256;
        sr[j] = chunk >> 3; scol[j] = (chunk & 7) * 4;
        agp[j] = aBase + (size_t)sr[j] * lda + scol[j];
        bgp[j] = bBase + (size_t)sr[j] * ldb + scol[j];
    }

    // prologue: chunk 0 into stage 0
    #pragma unroll
    for (int j = 0; j < 4; j++) {
        cp16(&As[0][sr[j]][scol[j]], agp[j]);
        cp16(&Bs[0][sr[j]][scol[j]], bgp[j]);
    }
    CP_COMMIT();
    CP_WAIT0();
    __syncthreads();

    const int aR = wm * 32 + (lmat & 1) * 8 + lrow;   // + mi*16
    const int bR = wn * 64 + (lmat & 1) * 8 + lrow;   // + np*16
    const int kO = (lmat >> 1) * 4;                   // + ks*8

    const int NK = EMBED / 32;   // 32 chunks
    for (int it = 0; it < NK; it++) {
        const int buf = it & 1;
        if (it + 1 < NK) {
            const int kc = (it + 1) * 32;
            #pragma unroll
            for (int j = 0; j < 4; j++) {
                cp16(&As[buf ^ 1][sr[j]][scol[j]], agp[j] + kc);
                cp16(&Bs[buf ^ 1][sr[j]][scol[j]], bgp[j] + kc);
            }
            CP_COMMIT();
        }

        #pragma unroll
        for (int ks = 0; ks < 4; ks++) {
            const int kb = ks * 8 + kO;
            uint32_t a[2][4], b[4][4];
            ldsm4(a[0], &As[buf][aR     ][kb]);
            ldsm4(a[1], &As[buf][aR + 16][kb]);
            #pragma unroll
            for (int np = 0; np < 4; np++)
                ldsm4(b[np], &Bs[buf][bR + np * 16][kb]);
            #pragma unroll
            for (int np = 0; np < 4; np++) {
                #pragma unroll
                for (int mi = 0; mi < 2; mi++) {
                    mma8(acc.c[mi][2 * np    ], a[mi][0], a[mi][1], a[mi][2], a[mi][3],
                         b[np][0], b[np][2]);
                    mma8(acc.c[mi][2 * np + 1], a[mi][0], a[mi][1], a[mi][2], a[mi][3],
                         b[np][1], b[np][3]);
                }
            }
        }

        if (it + 1 < NK) CP_WAIT0();
        __syncthreads();
    }
}

// ============================================================================
// Kernel 1: QKV GEMM -> scatter to g_q/g_k/g_v [B,H,S,D].
// ============================================================================
__global__ __launch_bounds__(256, 2) void qkv_kernel()
{
    const int n0 = blockIdx.x * 128;
    const int m0 = blockIdx.y * 128;

    GemmAcc acc;
    #pragma unroll
    for (int mi = 0; mi < 2; mi++)
        #pragma unroll
        for (int ni = 0; ni < 8; ni++)
            #pragma unroll
            for (int e = 0; e < 4; e++) acc.c[mi][ni][e] = 0.0f;

    gemm128_body(acc, g_xr + (size_t)m0 * EMBED, g_wqkv + (size_t)n0 * EMBED,
                 EMBED, EMBED);

    const int lane = threadIdx.x & 31;
    const int warp = threadIdx.x >> 5;
    const int g    = lane >> 2;
    const int t4   = lane & 3;
    const int wm   = warp & 3;
    const int wn   = warp >> 2;

    const int mat = n0 >> 10;
    const int b   = m0 >> 11;
    const int s0l = m0 & 2047;
    const int h   = ((n0 & 1023) >> 6) + wn;
    float* dstm = (mat == 0) ? g_q : ((mat == 1) ? g_k : g_v);
    float* dst  = dstm + ((size_t)(b * NHEADS + h) * SEQ) * HEAD;
    const float scale = (mat == 0) ? 0.125f : 1.0f;

    #pragma unroll
    for (int mi = 0; mi < 2; mi++) {
        int s0r = s0l + wm * 32 + mi * 16 + g;
        #pragma unroll
        for (int ni = 0; ni < 8; ni++) {
            int d = ni * 8 + t4 * 2;
            dst[(size_t)(s0r    ) * HEAD + d    ] = rnd32(acc.c[mi][ni][0] * scale);
            dst[(size_t)(s0r    ) * HEAD + d + 1] = rnd32(acc.c[mi][ni][1] * scale);
            dst[(size_t)(s0r + 8) * HEAD + d    ] = rnd32(acc.c[mi][ni][2] * scale);
            dst[(size_t)(s0r + 8) * HEAD + d + 1] = rnd32(acc.c[mi][ni][3] * scale);
        }
    }
}

// ============================================================================
// Kernel 2: causal flash attention (R9 version, proven).
// BM=128 (8 warps x 16 rows), BN=32, D=64, 3-stage cp.async K/V ring, occ 2.
// ============================================================================
__global__ __launch_bounds__(256, 2) void attn_kernel()
{
    extern __shared__ float smem[];
    float (*Ks)[32][68] = (float(*)[32][68])smem;
    float (*Vs)[32][72] = (float(*)[32][72])(smem + 3 * 32 * 68);
    float (*Ps)[36]     = (float(*)[36])(smem + 3 * 32 * 68 + 3 * 32 * 72);

    const int bh = blockIdx.y;
    const int b  = bh >> 4;
    const int h  = bh & 15;
    const int qt = blockIdx.x;
    const int q0 = qt * 128;

    const int tid  = threadIdx.x;
    const int lane = tid & 31;
    const int warp = tid >> 5;
    const int g    = lane >> 2;
    const int t4   = lane & 3;

    const float* qp = g_q + ((size_t)bh * SEQ + q0) * HEAD;
    const float* kp = g_k + (size_t)bh * SEQ * HEAD;
    const float* vp = g_v + (size_t)bh * SEQ * HEAD;

    int cr[2], cd[2];
    #pragma unroll
    for (int j = 0; j < 2; j++) {
        int chunk = tid + j * 256;
        cr[j] = chunk >> 4; cd[j] = (chunk & 15) * 4;
    }

    uint32_t qa[8][4];
    #pragma unroll
    for (int round = 0; round < 2; round++) {
        const int c0 = round * 32;
        #pragma unroll
        for (int i = tid; i < 128 * 32; i += 256) {
            int r = i >> 5, cc = i & 31;
            Ps[r][cc] = qp[(size_t)r * HEAD + c0 + cc];
        }
        __syncthreads();
        #pragma unroll
        for (int kf = 0; kf < 4; kf++) {
            int kfi = round * 4 + kf;
            int rr = warp * 16;
            qa[kfi][0] = __float_as_uint(Ps[rr + g    ][kf * 8 + t4]);
            qa[kfi][1] = __float_as_uint(Ps[rr + g + 8][kf * 8 + t4]);
            qa[kfi][2] = __float_as_uint(Ps[rr + g    ][kf * 8 + t4 + 4]);
            qa[kfi][3] = __float_as_uint(Ps[rr + g + 8][kf * 8 + t4 + 4]);
        }
        __syncthreads();
    }

    float o[8][4];
    #pragma unroll
    for (int dn = 0; dn < 8; dn++)
        #pragma unroll
        for (int e = 0; e < 4; e++) o[dn][e] = 0.0f;

    float m0 = -1e30f, m1 = -1e30f, l0 = 0.0f, l1 = 0.0f;

    const int nkt   = (qt + 1) * 4;
    const int row0b = q0 + warp * 16;
    const int qmaxw = row0b + 15;

    #pragma unroll
    for (int st = 0; st < 2; st++) {
        const size_t base = (size_t)st * 32 * HEAD;
        #pragma unroll
        for (int j = 0; j < 2; j++) {
            cp16(&Ks[st][cr[j]][cd[j]], kp + base + (size_t)cr[j] * HEAD + cd[j]);
            cp16(&Vs[st][cr[j]][cd[j]], vp + base + (size_t)cr[j] * HEAD + cd[j]);
        }
        CP_COMMIT();
    }

    int sc = 0;
    for (int kt = 0; kt < nkt; kt++) {
        const int k0 = kt * 32;

        CP_WAIT1();
        __syncthreads();

        if (kt + 2 < nkt) {
            int sp = sc + 2; if (sp >= 3) sp -= 3;
            const size_t base = (size_t)(k0 + 64) * HEAD;
            #pragma unroll
            for (int j = 0; j < 2; j++) {
                cp16(&Ks[sp][cr[j]][cd[j]], kp + base + (size_t)cr[j] * HEAD + cd[j]);
                cp16(&Vs[sp][cr[j]][cd[j]], vp + base + (size_t)cr[j] * HEAD + cd[j]);
            }
            CP_COMMIT();
        }

        if (k0 <= qmaxw) {
            float s[4][4];
            #pragma unroll
            for (int nf = 0; nf < 4; nf++)
                #pragma unroll
                for (int e = 0; e < 4; e++) s[nf][e] = 0.0f;

            #pragma unroll
            for (int kf = 0; kf < 8; kf++) {
                #pragma unroll
                for (int nf = 0; nf < 4; nf++) {
                    uint32_t b0 = __float_as_uint(Ks[sc][nf * 8 + g][kf * 8 + t4]);
                    uint32_t b1 = __float_as_uint(Ks[sc][nf * 8 + g][kf * 8 + t4 + 4]);
                    mma8(s[nf], qa[kf][0], qa[kf][1], qa[kf][2], qa[kf][3], b0, b1);
                }
            }

            const int r0 = row0b + g;
            const int r1 = r0 + 8;
            #pragma unroll
            for (int nf = 0; nf < 4; nf++) {
                int col0 = k0 + nf * 8 + t4 * 2;
                if (col0     > r0) s[nf][0] = -1e30f;
                if (col0 + 1 > r0) s[nf][1] = -1e30f;
                if (col0     > r1) s[nf][2] = -1e30f;
                if (col0 + 1 > r1) s[nf][3] = -1e30f;
            }

            float rm0 = -1e30f, rm1 = -1e30f;
            #pragma unroll
            for (int nf = 0; nf < 4; nf++) {
                rm0 = fmaxf(rm0, fmaxf(s[nf][0], s[nf][1]));
                rm1 = fmaxf(rm1, fmaxf(s[nf][2], s[nf][3]));
            }
            rm0 = fmaxf(rm0, __shfl_xor_sync(0xffffffffu, rm0, 1));
            rm0 = fmaxf(rm0, __shfl_xor_sync(0xffffffffu, rm0, 2));
            rm1 = fmaxf(rm1, __shfl_xor_sync(0xffffffffu, rm1, 1));
            rm1 = fmaxf(rm1, __shfl_xor_sync(0xffffffffu, rm1, 2));

            float nm0 = fmaxf(m0, rm0), nm1 = fmaxf(m1, rm1);
            float sc0 = __expf(m0 - nm0), sc1 = __expf(m1 - nm1);

            float sum0 = 0.0f, sum1 = 0.0f;
            const int rr = warp * 16;
            #pragma unroll
            for (int nf = 0; nf < 4; nf++) {
                float p0 = rnd32(__expf(s[nf][0] - nm0));
                float p1 = rnd32(__expf(s[nf][1] - nm0));
                float p2 = rnd32(__expf(s[nf][2] - nm1));
                float p3 = rnd32(__expf(s[nf][3] - nm1));
                Ps[rr + g    ][nf * 8 + t4 * 2    ] = p0;
                Ps[rr + g    ][nf * 8 + t4 * 2 + 1] = p1;
                Ps[rr + g + 8][nf * 8 + t4 * 2    ] = p2;
                Ps[rr + g + 8][nf * 8 + t4 * 2 + 1] = p3;
                sum0 += p0 + p1;
                sum1 += p2 + p3;
            }
            sum0 += __shfl_xor_sync(0xffffffffu, sum0, 1);
            sum0 += __shfl_xor_sync(0xffffffffu, sum0, 2);
            sum1 += __shfl_xor_sync(0xffffffffu, sum1, 1);
            sum1 += __shfl_xor_sync(0xffffffffu, sum1, 2);

            l0 = l0 * sc0 + sum0;  m0 = nm0;
            l1 = l1 * sc1 + sum1;  m1 = nm1;

            #pragma unroll
            for (int dn = 0; dn < 8; dn++) {
                o[dn][0] *= sc0; o[dn][1] *= sc0;
                o[dn][2] *= sc1; o[dn][3] *= sc1;
            }
            __syncwarp();

            #pragma unroll
            for (int kf = 0; kf < 4; kf++) {
                uint32_t pa0 = __float_as_uint(Ps[rr + g    ][kf * 8 + t4]);
                uint32_t pa1 = __float_as_uint(Ps[rr + g + 8][kf * 8 + t4]);
                uint32_t pa2 = __float_as_uint(Ps[rr + g    ][kf * 8 + t4 + 4]);
                uint32_t pa3 = __float_as_uint(Ps[rr + g + 8][kf * 8 + t4 + 4]);
                #pragma unroll
                for (int dn = 0; dn < 8; dn++) {
                    uint32_t b0 = __float_as_uint(Vs[sc][kf * 8 + t4    ][dn * 8 + g]);
                    uint32_t b1 = __float_as_uint(Vs[sc][kf * 8 + t4 + 4][dn * 8 + g]);
                    mma8(o[dn], pa0, pa1, pa2, pa3, b0, b1);
                }
            }
            __syncwarp();
        }

        if (++sc == 3) sc = 0;
    }

    const float inv0 = 1.0f / l0;
    const float inv1 = 1.0f / l1;
    const int r0 = q0 + warp * 16 + g;
    float* ob = g_attn + (size_t)b * SEQ * EMBED + (size_t)h * HEAD;
    #pragma unroll
    for (int dn = 0; dn < 8; dn++) {
        int d = dn * 8 + t4 * 2;
        ob[(size_t)(r0    ) * EMBED + d    ] = rnd32(o[dn][0] * inv0);
        ob[(size_t)(r0    ) * EMBED + d + 1] = rnd32(o[dn][1] * inv0);
        ob[(size_t)(r0 + 8) * EMBED + d    ] = rnd32(o[dn][2] * inv1);
        ob[(size_t)(r0 + 8) * EMBED + d + 1] = rnd32(o[dn][3] * inv1);
    }
}

// ============================================================================
// Kernel 3: output projection.  out[m][e] = sum_f attn[m][f]*Wo[e][f] + bo[e].
// B operand = raw (rounded) Wo: B[n=e][k=f].
// ============================================================================
__global__ __launch_bounds__(256, 2) void proj_kernel(
    const float* __restrict__ bo,
    float* __restrict__ out)
{
    const int e0 = blockIdx.x * 128;
    const int m0 = blockIdx.y * 128;

    GemmAcc acc;
    #pragma unroll
    for (int mi = 0; mi < 2; mi++)
        #pragma unroll
        for (int ni = 0; ni < 8; ni++)
            #pragma unroll
            for (int e = 0; e < 4; e++) acc.c[mi][ni][e] = 0.0f;

    gemm128_body(acc, g_attn + (size_t)m0 * EMBED, g_wo + (size_t)e0 * EMBED,
                 EMBED, EMBED);

    const int lane = threadIdx.x & 31;
    const int warp = threadIdx.x >> 5;
    const int g    = lane >> 2;
    const int t4   = lane & 3;
    const int wm   = warp & 3;
    const int wn   = warp >> 2;

    #pragma unroll
    for (int mi = 0; mi < 2; mi++) {
        int r0 = m0 + wm * 32 + mi * 16 + g;
        #pragma unroll
        for (int ni = 0; ni < 8; ni++) {
            int e = e0 + wn * 64 + ni * 8 + t4 * 2;
            out[(size_t)(r0    ) * EMBED + e    ] = acc.c[mi][ni][0] + bo[e];
            out[(size_t)(r0    ) * EMBED + e + 1] = acc.c[mi][ni][1] + bo[e + 1];
            out[(size_t)(r0 + 8) * EMBED + e    ] = acc.c[mi][ni][2] + bo[e];
            out[(size_t)(r0 + 8) * EMBED + e + 1] = acc.c[mi][ni][3] + bo[e + 1];
        }
    }
}

// ============================================================================
extern "C" void kernel_launch(void* const* d_in, const int* in_sizes, int n_in,
                              void* d_out, int out_size)
{
    const float* x  = (const float*)d_in[0];
    const float* Wq = (const float*)d_in[1];
    const float* Wk = (const float*)d_in[2];
    const float* Wv = (const float*)d_in[3];
    const float* Wo = (const float*)d_in[4];
    const float* bo = (const float*)d_in[5];
    float* out = (float*)d_out;

    (void)in_sizes; (void)n_in; (void)out_size;

    cudaFuncSetAttribute(qkv_kernel,  cudaFuncAttributeMaxDynamicSharedMemorySize, GEMM_SMEM);
    cudaFuncSetAttribute(attn_kernel, cudaFuncAttributeMaxDynamicSharedMemorySize, ATTN_SMEM);
    cudaFuncSetAttribute(proj_kernel, cudaFuncAttributeMaxDynamicSharedMemorySize, GEMM_SMEM);

    round_x_kernel<<<NTOK * EMBED / 1024, 256>>>(x);
    pack_w_kernel<<<QKVN * EMBED / 256, 256>>>(Wq, Wk, Wv);
    round_wo_kernel<<<EMBED * EMBED / 1024, 256>>>(Wo);

    qkv_kernel<<<dim3(QKVN / 128, NTOK / 128), 256, GEMM_SMEM>>>();
    attn_kernel<<<dim3(SEQ / 128, BATCH * NHEADS), 256, ATTN_SMEM>>>();
    proj_kernel<<<dim3(EMBED / 128, NTOK / 128), 256, GEMM_SMEM>>>(bo, out);
}

// round 11
// speedup vs baseline: 1.3378x; 1.3378x over previous
#include <cuda_runtime.h>
#include <cuda_fp16.h>
#include <stdint.h>
#include <math.h>

#define BATCH  4
#define NHEADS 16
#define HEAD   64
#define SEQ    2048
#define EMBED  1024
#define QKVN   3072
#define NTOK   (BATCH * SEQ)   // 8192
#define HPAD   72              // half-row pad: 144B, ldmatrix phase conflict-free

// ---------------- scratch (device globals: allocation-free) ----------------
__device__ float  g_q[BATCH * NHEADS * SEQ * HEAD];   // [B,H,S,D] fp32 tf32-rounded, Q pre-scaled
__device__ float  g_k[BATCH * NHEADS * SEQ * HEAD];
__device__ float  g_v[BATCH * NHEADS * SEQ * HEAD];
__device__ __half g_attnh[BATCH * SEQ * EMBED];       // [B,S,H*D] fp16
__device__ __half g_xh[NTOK * EMBED];                 // X fp16
__device__ __half g_wqkvh[QKVN * EMBED];              // packed [n][k] fp16
__device__ __half g_woh[EMBED * EMBED];               // Wo [e][f] fp16

// ---------------- helpers ----------------
__device__ __forceinline__ float rnd32(float f) {
    uint32_t r;
    asm("cvt.rna.tf32.f32 %0, %1;" : "=r"(r) : "f"(f));
    return __uint_as_float(r);
}

// tf32 m16n8k8 (attention)
__device__ __forceinline__ void mma8(float* c,
                                     uint32_t a0, uint32_t a1, uint32_t a2, uint32_t a3,
                                     uint32_t b0, uint32_t b1) {
    asm volatile(
        "mma.sync.aligned.m16n8k8.row.col.f32.tf32.tf32.f32 "
        "{%0,%1,%2,%3}, {%4,%5,%6,%7}, {%8,%9}, {%0,%1,%2,%3};"
        : "+f"(c[0]), "+f"(c[1]), "+f"(c[2]), "+f"(c[3])
        : "r"(a0), "r"(a1), "r"(a2), "r"(a3), "r"(b0), "r"(b1));
}

// fp16 m16n8k16, fp32 accum (GEMMs)
__device__ __forceinline__ void mma16(float* c,
                                      uint32_t a0, uint32_t a1, uint32_t a2, uint32_t a3,
                                      uint32_t b0, uint32_t b1) {
    asm volatile(
        "mma.sync.aligned.m16n8k16.row.col.f32.f16.f16.f32 "
        "{%0,%1,%2,%3}, {%4,%5,%6,%7}, {%8,%9}, {%0,%1,%2,%3};"
        : "+f"(c[0]), "+f"(c[1]), "+f"(c[2]), "+f"(c[3])
        : "r"(a0), "r"(a1), "r"(a2), "r"(a3), "r"(b0), "r"(b1));
}

__device__ __forceinline__ void ldsm4(uint32_t* r, const void* p) {
    uint32_t a = (uint32_t)__cvta_generic_to_shared(p);
    asm volatile("ldmatrix.sync.aligned.m8n8.x4.shared.b16 {%0,%1,%2,%3}, [%4];"
                 : "=r"(r[0]), "=r"(r[1]), "=r"(r[2]), "=r"(r[3]) : "r"(a));
}

__device__ __forceinline__ void cp16(void* smem, const void* gmem) {
    uint32_t sa = (uint32_t)__cvta_generic_to_shared(smem);
    asm volatile("cp.async.cg.shared.global [%0], [%1], 16;" :: "r"(sa), "l"(gmem));
}
#define CP_COMMIT() asm volatile("cp.async.commit_group;")
#define CP_WAIT0()  asm volatile("cp.async.wait_group 0;")
#define CP_WAIT1()  asm volatile("cp.async.wait_group 1;")

// smem sizes (bytes)
#define GEMM_SMEM (2 * 2 * 128 * HPAD * 2)                       // 73728
#define ATTN_SMEM ((3 * 32 * 68 + 3 * 32 * 72 + 128 * 36) * 4)   // 72192

// ============================================================================
// Prep kernels: convert operands to fp16 once.
// ============================================================================
__global__ __launch_bounds__(256) void x2h_kernel(const float* __restrict__ x) {
    int i = (blockIdx.x * 256 + threadIdx.x) * 4;
    float4 v = *(const float4*)(x + i);
    __half2 h0 = __floats2half2_rn(v.x, v.y);
    __half2 h1 = __floats2half2_rn(v.z, v.w);
    *(__half2*)(g_xh + i)     = h0;
    *(__half2*)(g_xh + i + 2) = h1;
}

// g_wqkvh[n][k]: n -> (mat, head, d)
__global__ __launch_bounds__(256) void packw_kernel(
    const float* __restrict__ Wq, const float* __restrict__ Wk, const float* __restrict__ Wv) {
    int i = blockIdx.x * 256 + threadIdx.x;      // over QKVN*EMBED
    int n = i >> 10;
    int k = i & 1023;
    int mat = n >> 10;
    int hn  = n & 1023;
    int h = hn >> 6, d = hn & 63;
    const float* w = (mat == 0) ? Wq : ((mat == 1) ? Wk : Wv);
    g_wqkvh[i] = __float2half_rn(w[((size_t)h * EMBED + k) * HEAD + d]);
}

__global__ __launch_bounds__(256) void wo2h_kernel(const float* __restrict__ Wo) {
    int i = (blockIdx.x * 256 + threadIdx.x) * 4;
    float4 v = *(const float4*)(Wo + i);
    __half2 h0 = __floats2half2_rn(v.x, v.y);
    __half2 h1 = __floats2half2_rn(v.z, v.w);
    *(__half2*)(g_woh + i)     = h0;
    *(__half2*)(g_woh + i + 2) = h1;
}

// ============================================================================
// fp16 GEMM body: C[128x128] = A[128xK] * B^T  (A [m][k], B [n][k], both
// k-contiguous fp16).  K-chunk 64, 2-stage.  8 warps = 4(M) x 2(N), warp 32x64.
// m16n8k16 mma, ldmatrix.x4 b16 fragments.
// ============================================================================
struct GemmAcc { float c[2][8][4]; };

__device__ __forceinline__ void gemm128h(
    GemmAcc& acc,
    const __half* __restrict__ aBase,
    const __half* __restrict__ bBase,
    int lda, int ldb)
{
    extern __shared__ __half sh[];
    __half (*As)[128][HPAD] = (__half(*)[128][HPAD])sh;
    __half (*Bs)[128][HPAD] = (__half(*)[128][HPAD])(sh + 2 * 128 * HPAD);

    const int tid  = threadIdx.x;
    const int lane = tid & 31;
    const int warp = tid >> 5;
    const int wm   = warp & 3;         // M: 4 warps x 32 rows
    const int wn   = warp >> 2;        // N: 2 warps x 64 cols
    const int fr   = lane & 15;        // fragment row within 16
    const int fk   = (lane >> 4) * 8;  // fragment k offset 0/8

    // staging: 128 rows x 64 halves = 1024 x 16B chunks; 4 chunks/thread each
    int sr[4], scol[4];
    const __half* agp[4];
    const __half* bgp[4];
    #pragma unroll
    for (int j = 0; j < 4; j++) {
        int chunk = tid + j * 256;
        sr[j] = chunk >> 3; scol[j] = (chunk & 7) * 8;
        agp[j] = aBase + (size_t)sr[j] * lda + scol[j];
        bgp[j] = bBase + (size_t)sr[j] * ldb + scol[j];
    }

    // prologue
    #pragma unroll
    for (int j = 0; j < 4; j++) {
        cp16(&As[0][sr[j]][scol[j]], agp[j]);
        cp16(&Bs[0][sr[j]][scol[j]], bgp[j]);
    }
    CP_COMMIT();
    CP_WAIT0();
    __syncthreads();

    const int NK = EMBED / 64;   // 16 chunks
    for (int it = 0; it < NK; it++) {
        const int buf = it & 1;
        if (it + 1 < NK) {
            const int kc = (it + 1) * 64;
            #pragma unroll
            for (int j = 0; j < 4; j++) {
                cp16(&As[buf ^ 1][sr[j]][scol[j]], agp[j] + kc);
                cp16(&Bs[buf ^ 1][sr[j]][scol[j]], bgp[j] + kc);
            }
            CP_COMMIT();
        }

        #pragma unroll
        for (int ks = 0; ks < 4; ks++) {
            const int k0 = ks * 16 + fk;
            uint32_t a[2][4], b[4][4];
            #pragma unroll
            for (int mi = 0; mi < 2; mi++)
                ldsm4(a[mi], &As[buf][wm * 32 + mi * 16 + fr][k0]);
            #pragma unroll
            for (int np = 0; np < 4; np++)
                ldsm4(b[np], &Bs[buf][wn * 64 + np * 16 + fr][k0]);
            // b[np]: r0=(n0-7,k0-7) r1=(n8-15,k0-7) r2=(n0-7,k8-15) r3=(n8-15,k8-15)
            #pragma unroll
            for (int np = 0; np < 4; np++) {
                #pragma unroll
                for (int mi = 0; mi < 2; mi++) {
                    mma16(acc.c[mi][2 * np    ], a[mi][0], a[mi][1], a[mi][2], a[mi][3],
                          b[np][0], b[np][2]);
                    mma16(acc.c[mi][2 * np + 1], a[mi][0], a[mi][1], a[mi][2], a[mi][3],
                          b[np][1], b[np][3]);
                }
            }
        }

        if (it + 1 < NK) CP_WAIT0();
        __syncthreads();
    }
}

// ============================================================================
// Kernel 1: QKV GEMM (fp16) -> scatter fp32 tf32-rounded to g_q/g_k/g_v.
// ============================================================================
__global__ __launch_bounds__(256, 2) void qkv_kernel()
{
    const int n0 = blockIdx.x * 128;
    const int m0 = blockIdx.y * 128;

    GemmAcc acc;
    #pragma unroll
    for (int mi = 0; mi < 2; mi++)
        #pragma unroll
        for (int ni = 0; ni < 8; ni++)
            #pragma unroll
            for (int e = 0; e < 4; e++) acc.c[mi][ni][e] = 0.0f;

    gemm128h(acc, g_xh + (size_t)m0 * EMBED, g_wqkvh + (size_t)n0 * EMBED,
             EMBED, EMBED);

    const int lane = threadIdx.x & 31;
    const int warp = threadIdx.x >> 5;
    const int g    = lane >> 2;
    const int t4   = lane & 3;
    const int wm   = warp & 3;
    const int wn   = warp >> 2;

    const int mat = n0 >> 10;
    const int b   = m0 >> 11;
    const int s0l = m0 & 2047;
    const int h   = ((n0 & 1023) >> 6) + wn;
    float* dstm = (mat == 0) ? g_q : ((mat == 1) ? g_k : g_v);
    float* dst  = dstm + ((size_t)(b * NHEADS + h) * SEQ) * HEAD;
    const float scale = (mat == 0) ? 0.125f : 1.0f;

    #pragma unroll
    for (int mi = 0; mi < 2; mi++) {
        int s0r = s0l + wm * 32 + mi * 16 + g;
        #pragma unroll
        for (int ni = 0; ni < 8; ni++) {
            int d = ni * 8 + t4 * 2;
            dst[(size_t)(s0r    ) * HEAD + d    ] = rnd32(acc.c[mi][ni][0] * scale);
            dst[(size_t)(s0r    ) * HEAD + d + 1] = rnd32(acc.c[mi][ni][1] * scale);
            dst[(size_t)(s0r + 8) * HEAD + d    ] = rnd32(acc.c[mi][ni][2] * scale);
            dst[(size_t)(s0r + 8) * HEAD + d + 1] = rnd32(acc.c[mi][ni][3] * scale);
        }
    }
}

// ============================================================================
// Kernel 2: causal flash attention (R9 tf32 core, proven; epilogue -> fp16).
// BM=128 (8 warps x 16 rows), BN=32, D=64, 3-stage cp.async K/V ring, occ 2.
// ============================================================================
__global__ __launch_bounds__(256, 2) void attn_kernel()
{
    extern __shared__ float smem[];
    float (*Ks)[32][68] = (float(*)[32][68])smem;
    float (*Vs)[32][72] = (float(*)[32][72])(smem + 3 * 32 * 68);
    float (*Ps)[36]     = (float(*)[36])(smem + 3 * 32 * 68 + 3 * 32 * 72);

    const int bh = blockIdx.y;
    const int b  = bh >> 4;
    const int h  = bh & 15;
    const int qt = blockIdx.x;
    const int q0 = qt * 128;

    const int tid  = threadIdx.x;
    const int lane = tid & 31;
    const int warp = tid >> 5;
    const int g    = lane >> 2;
    const int t4   = lane & 3;

    const float* qp = g_q + ((size_t)bh * SEQ + q0) * HEAD;
    const float* kp = g_k + (size_t)bh * SEQ * HEAD;
    const float* vp = g_v + (size_t)bh * SEQ * HEAD;

    int cr[2], cd[2];
    #pragma unroll
    for (int j = 0; j < 2; j++) {
        int chunk = tid + j * 256;
        cr[j] = chunk >> 4; cd[j] = (chunk & 15) * 4;
    }

    uint32_t qa[8][4];
    #pragma unroll
    for (int round = 0; round < 2; round++) {
        const int c0 = round * 32;
        #pragma unroll
        for (int i = tid; i < 128 * 32; i += 256) {
            int r = i >> 5, cc = i & 31;
            Ps[r][cc] = qp[(size_t)r * HEAD + c0 + cc];
        }
        __syncthreads();
        #pragma unroll
        for (int kf = 0; kf < 4; kf++) {
            int kfi = round * 4 + kf;
            int rr = warp * 16;
            qa[kfi][0] = __float_as_uint(Ps[rr + g    ][kf * 8 + t4]);
            qa[kfi][1] = __float_as_uint(Ps[rr + g + 8][kf * 8 + t4]);
            qa[kfi][2] = __float_as_uint(Ps[rr + g    ][kf * 8 + t4 + 4]);
            qa[kfi][3] = __float_as_uint(Ps[rr + g + 8][kf * 8 + t4 + 4]);
        }
        __syncthreads();
    }

    float o[8][4];
    #pragma unroll
    for (int dn = 0; dn < 8; dn++)
        #pragma unroll
        for (int e = 0; e < 4; e++) o[dn][e] = 0.0f;

    float m0 = -1e30f, m1 = -1e30f, l0 = 0.0f, l1 = 0.0f;

    const int nkt   = (qt + 1) * 4;
    const int row0b = q0 + warp * 16;
    const int qmaxw = row0b + 15;

    #pragma unroll
    for (int st = 0; st < 2; st++) {
        const size_t base = (size_t)st * 32 * HEAD;
        #pragma unroll
        for (int j = 0; j < 2; j++) {
            cp16(&Ks[st][cr[j]][cd[j]], kp + base + (size_t)cr[j] * HEAD + cd[j]);
            cp16(&Vs[st][cr[j]][cd[j]], vp + base + (size_t)cr[j] * HEAD + cd[j]);
        }
        CP_COMMIT();
    }

    int sc = 0;
    for (int kt = 0; kt < nkt; kt++) {
        const int k0 = kt * 32;

        CP_WAIT1();
        __syncthreads();

        if (kt + 2 < nkt) {
            int sp = sc + 2; if (sp >= 3) sp -= 3;
            const size_t base = (size_t)(k0 + 64) * HEAD;
            #pragma unroll
            for (int j = 0; j < 2; j++) {
                cp16(&Ks[sp][cr[j]][cd[j]], kp + base + (size_t)cr[j] * HEAD + cd[j]);
                cp16(&Vs[sp][cr[j]][cd[j]], vp + base + (size_t)cr[j] * HEAD + cd[j]);
            }
            CP_COMMIT();
        }

        if (k0 <= qmaxw) {
            float s[4][4];
            #pragma unroll
            for (int nf = 0; nf < 4; nf++)
                #pragma unroll
                for (int e = 0; e < 4; e++) s[nf][e] = 0.0f;

            #pragma unroll
            for (int kf = 0; kf < 8; kf++) {
                #pragma unroll
                for (int nf = 0; nf < 4; nf++) {
                    uint32_t b0 = __float_as_uint(Ks[sc][nf * 8 + g][kf * 8 + t4]);
                    uint32_t b1 = __float_as_uint(Ks[sc][nf * 8 + g][kf * 8 + t4 + 4]);
                    mma8(s[nf], qa[kf][0], qa[kf][1], qa[kf][2], qa[kf][3], b0, b1);
                }
            }

            const int r0 = row0b + g;
            const int r1 = r0 + 8;
            #pragma unroll
            for (int nf = 0; nf < 4; nf++) {
                int col0 = k0 + nf * 8 + t4 * 2;
                if (col0     > r0) s[nf][0] = -1e30f;
                if (col0 + 1 > r0) s[nf][1] = -1e30f;
                if (col0     > r1) s[nf][2] = -1e30f;
                if (col0 + 1 > r1) s[nf][3] = -1e30f;
            }

            float rm0 = -1e30f, rm1 = -1e30f;
            #pragma unroll
            for (int nf = 0; nf < 4; nf++) {
                rm0 = fmaxf(rm0, fmaxf(s[nf][0], s[nf][1]));
                rm1 = fmaxf(rm1, fmaxf(s[nf][2], s[nf][3]));
            }
            rm0 = fmaxf(rm0, __shfl_xor_sync(0xffffffffu, rm0, 1));
            rm0 = fmaxf(rm0, __shfl_xor_sync(0xffffffffu, rm0, 2));
            rm1 = fmaxf(rm1, __shfl_xor_sync(0xffffffffu, rm1, 1));
            rm1 = fmaxf(rm1, __shfl_xor_sync(0xffffffffu, rm1, 2));

            float nm0 = fmaxf(m0, rm0), nm1 = fmaxf(m1, rm1);
            float sc0 = __expf(m0 - nm0), sc1 = __expf(m1 - nm1);

            float sum0 = 0.0f, sum1 = 0.0f;
            const int rr = warp * 16;
            #pragma unroll
            for (int nf = 0; nf < 4; nf++) {
                float p0 = rnd32(__expf(s[nf][0] - nm0));
                float p1 = rnd32(__expf(s[nf][1] - nm0));
                float p2 = rnd32(__expf(s[nf][2] - nm1));
                float p3 = rnd32(__expf(s[nf][3] - nm1));
                Ps[rr + g    ][nf * 8 + t4 * 2    ] = p0;
                Ps[rr + g    ][nf * 8 + t4 * 2 + 1] = p1;
                Ps[rr + g + 8][nf * 8 + t4 * 2    ] = p2;
                Ps[rr + g + 8][nf * 8 + t4 * 2 + 1] = p3;
                sum0 += p0 + p1;
                sum1 += p2 + p3;
            }
            sum0 += __shfl_xor_sync(0xffffffffu, sum0, 1);
            sum0 += __shfl_xor_sync(0xffffffffu, sum0, 2);
            sum1 += __shfl_xor_sync(0xffffffffu, sum1, 1);
            sum1 += __shfl_xor_sync(0xffffffffu, sum1, 2);

            l0 = l0 * sc0 + sum0;  m0 = nm0;
            l1 = l1 * sc1 + sum1;  m1 = nm1;

            #pragma unroll
            for (int dn = 0; dn < 8; dn++) {
                o[dn][0] *= sc0; o[dn][1] *= sc0;
                o[dn][2] *= sc1; o[dn][3] *= sc1;
            }
            __syncwarp();

            #pragma unroll
            for (int kf = 0; kf < 4; kf++) {
                uint32_t pa0 = __float_as_uint(Ps[rr + g    ][kf * 8 + t4]);
                uint32_t pa1 = __float_as_uint(Ps[rr + g + 8][kf * 8 + t4]);
                uint32_t pa2 = __float_as_uint(Ps[rr + g    ][kf * 8 + t4 + 4]);
                uint32_t pa3 = __float_as_uint(Ps[rr + g + 8][kf * 8 + t4 + 4]);
                #pragma unroll
                for (int dn = 0; dn < 8; dn++) {
                    uint32_t b0 = __float_as_uint(Vs[sc][kf * 8 + t4    ][dn * 8 + g]);
                    uint32_t b1 = __float_as_uint(Vs[sc][kf * 8 + t4 + 4][dn * 8 + g]);
                    mma8(o[dn], pa0, pa1, pa2, pa3, b0, b1);
                }
            }
            __syncwarp();
        }

        if (++sc == 3) sc = 0;
    }

    // epilogue: normalize, write fp16 [B,S,H,D]
    const float inv0 = 1.0f / l0;
    const float inv1 = 1.0f / l1;
    const int r0 = q0 + warp * 16 + g;
    __half* ob = g_attnh + (size_t)b * SEQ * EMBED + (size_t)h * HEAD;
    #pragma unroll
    for (int dn = 0; dn < 8; dn++) {
        int d = dn * 8 + t4 * 2;
        *(__half2*)(ob + (size_t)(r0    ) * EMBED + d) =
            __floats2half2_rn(o[dn][0] * inv0, o[dn][1] * inv0);
        *(__half2*)(ob + (size_t)(r0 + 8) * EMBED + d) =
            __floats2half2_rn(o[dn][2] * inv1, o[dn][3] * inv1);
    }
}

// ============================================================================
// Kernel 3: output projection (fp16).  out[m][e] = attn[m][:]·Wo[e][:] + bo[e].
// ============================================================================
__global__ __launch_bounds__(256, 2) void proj_kernel(
    const float* __restrict__ bo,
    float* __restrict__ out)
{
    const int e0 = blockIdx.x * 128;
    const int m0 = blockIdx.y * 128;

    GemmAcc acc;
    #pragma unroll
    for (int mi = 0; mi < 2; mi++)
        #pragma unroll
        for (int ni = 0; ni < 8; ni++)
            #pragma unroll
            for (int e = 0; e < 4; e++) acc.c[mi][ni][e] = 0.0f;

    gemm128h(acc, g_attnh + (size_t)m0 * EMBED, g_woh + (size_t)e0 * EMBED,
             EMBED, EMBED);

    const int lane = threadIdx.x & 31;
    const int warp = threadIdx.x >> 5;
    const int g    = lane >> 2;
    const int t4   = lane & 3;
    const int wm   = warp & 3;
    const int wn   = warp >> 2;

    #pragma unroll
    for (int mi = 0; mi < 2; mi++) {
        int r0 = m0 + wm * 32 + mi * 16 + g;
        #pragma unroll
        for (int ni = 0; ni < 8; ni++) {
            int e = e0 + wn * 64 + ni * 8 + t4 * 2;
            out[(size_t)(r0    ) * EMBED + e    ] = acc.c[mi][ni][0] + bo[e];
            out[(size_t)(r0    ) * EMBED + e + 1] = acc.c[mi][ni][1] + bo[e + 1];
            out[(size_t)(r0 + 8) * EMBED + e    ] = acc.c[mi][ni][2] + bo[e];
            out[(size_t)(r0 + 8) * EMBED + e + 1] = acc.c[mi][ni][3] + bo[e + 1];
        }
    }
}

// ============================================================================
extern "C" void kernel_launch(void* const* d_in, const int* in_sizes, int n_in,
                              void* d_out, int out_size)
{
    const float* x  = (const float*)d_in[0];
    const float* Wq = (const float*)d_in[1];
    const float* Wk = (const float*)d_in[2];
    const float* Wv = (const float*)d_in[3];
    const float* Wo = (const float*)d_in[4];
    const float* bo = (const float*)d_in[5];
    float* out = (float*)d_out;

    (void)in_sizes; (void)n_in; (void)out_size;

    cudaFuncSetAttribute(qkv_kernel,  cudaFuncAttributeMaxDynamicSharedMemorySize, GEMM_SMEM);
    cudaFuncSetAttribute(attn_kernel, cudaFuncAttributeMaxDynamicSharedMemorySize, ATTN_SMEM);
    cudaFuncSetAttribute(proj_kernel, cudaFuncAttributeMaxDynamicSharedMemorySize, GEMM_SMEM);

    x2h_kernel<<<NTOK * EMBED / 1024, 256>>>(x);
    packw_kernel<<<QKVN * EMBED / 256, 256>>>(Wq, Wk, Wv);
    wo2h_kernel<<<EMBED * EMBED / 1024, 256>>>(Wo);

    qkv_kernel<<<dim3(QKVN / 128, NTOK / 128), 256, GEMM_SMEM>>>();
    attn_kernel<<<dim3(SEQ / 128, BATCH * NHEADS), 256, ATTN_SMEM>>>();
    proj_kernel<<<dim3(EMBED / 128, NTOK / 128), 256, GEMM_SMEM>>>(bo, out);
}

// round 12
// speedup vs baseline: 1.8113x; 1.3539x over previous
#include <cuda_runtime.h>
#include <cuda_fp16.h>
#include <stdint.h>
#include <math.h>

#define BATCH  4
#define NHEADS 16
#define HEAD   64
#define SEQ    2048
#define EMBED  1024
#define QKVN   3072
#define NTOK   (BATCH * SEQ)   // 8192
#define HPAD   72              // half-row pad: 144B, ldmatrix phase conflict-free

// ---------------- scratch (device globals: allocation-free) ----------------
__device__ __half g_qh[BATCH * NHEADS * SEQ * HEAD];  // [B,H,S,D] fp16, pre-scaled
__device__ __half g_kh[BATCH * NHEADS * SEQ * HEAD];  // [B,H,S,D] fp16
__device__ __half g_vh[BATCH * NHEADS * HEAD * SEQ];  // [B,H,D,S] fp16 (transposed)
__device__ __half g_attnh[BATCH * SEQ * EMBED];       // [B,S,H*D] fp16
__device__ __half g_xh[NTOK * EMBED];                 // X fp16
__device__ __half g_wqkvh[QKVN * EMBED];              // packed [n][k] fp16
__device__ __half g_woh[EMBED * EMBED];               // Wo [e][f] fp16

// ---------------- helpers ----------------
// fp16 m16n8k16, fp32 accum
__device__ __forceinline__ void mma16(float* c,
                                      uint32_t a0, uint32_t a1, uint32_t a2, uint32_t a3,
                                      uint32_t b0, uint32_t b1) {
    asm volatile(
        "mma.sync.aligned.m16n8k16.row.col.f32.f16.f16.f32 "
        "{%0,%1,%2,%3}, {%4,%5,%6,%7}, {%8,%9}, {%0,%1,%2,%3};"
        : "+f"(c[0]), "+f"(c[1]), "+f"(c[2]), "+f"(c[3])
        : "r"(a0), "r"(a1), "r"(a2), "r"(a3), "r"(b0), "r"(b1));
}

__device__ __forceinline__ void ldsm4(uint32_t* r, const void* p) {
    uint32_t a = (uint32_t)__cvta_generic_to_shared(p);
    asm volatile("ldmatrix.sync.aligned.m8n8.x4.shared.b16 {%0,%1,%2,%3}, [%4];"
                 : "=r"(r[0]), "=r"(r[1]), "=r"(r[2]), "=r"(r[3]) : "r"(a));
}

__device__ __forceinline__ void cp16(void* smem, const void* gmem) {
    uint32_t sa = (uint32_t)__cvta_generic_to_shared(smem);
    asm volatile("cp.async.cg.shared.global [%0], [%1], 16;" :: "r"(sa), "l"(gmem));
}
#define CP_COMMIT() asm volatile("cp.async.commit_group;")
#define CP_WAIT0()  asm volatile("cp.async.wait_group 0;")
#define CP_WAIT1()  asm volatile("cp.async.wait_group 1;")

__device__ __forceinline__ uint32_t h2u(__half2 h) { return *(uint32_t*)&h; }

// smem sizes (bytes)
#define GEMM_SMEM (2 * 2 * 128 * HPAD * 2)                           // 73728
#define ATTN_SMEM ((128 * 72 + 3 * 32 * 72 + 3 * 64 * 40) * 2)      // 47616

// ============================================================================
// Prep kernels: convert operands to fp16 once.
// ============================================================================
__global__ __launch_bounds__(256) void x2h_kernel(const float* __restrict__ x) {
    int i = (blockIdx.x * 256 + threadIdx.x) * 4;
    float4 v = *(const float4*)(x + i);
    *(__half2*)(g_xh + i)     = __floats2half2_rn(v.x, v.y);
    *(__half2*)(g_xh + i + 2) = __floats2half2_rn(v.z, v.w);
}

__global__ __launch_bounds__(256) void packw_kernel(
    const float* __restrict__ Wq, const float* __restrict__ Wk, const float* __restrict__ Wv) {
    int i = blockIdx.x * 256 + threadIdx.x;      // over QKVN*EMBED
    int n = i >> 10;
    int k = i & 1023;
    int mat = n >> 10;
    int hn  = n & 1023;
    int h = hn >> 6, d = hn & 63;
    const float* w = (mat == 0) ? Wq : ((mat == 1) ? Wk : Wv);
    g_wqkvh[i] = __float2half_rn(w[((size_t)h * EMBED + k) * HEAD + d]);
}

__global__ __launch_bounds__(256) void wo2h_kernel(const float* __restrict__ Wo) {
    int i = (blockIdx.x * 256 + threadIdx.x) * 4;
    float4 v = *(const float4*)(Wo + i);
    *(__half2*)(g_woh + i)     = __floats2half2_rn(v.x, v.y);
    *(__half2*)(g_woh + i + 2) = __floats2half2_rn(v.z, v.w);
}

// ============================================================================
// fp16 GEMM body (R11, proven): C[128x128] = A[128xK] * B^T.
// K-chunk 64, 2-stage.  8 warps = 4(M) x 2(N), warp 32x64.
// ============================================================================
struct GemmAcc { float c[2][8][4]; };

__device__ __forceinline__ void gemm128h(
    GemmAcc& acc,
    const __half* __restrict__ aBase,
    const __half* __restrict__ bBase,
    int lda, int ldb)
{
    extern __shared__ __half sh[];
    __half (*As)[128][HPAD] = (__half(*)[128][HPAD])sh;
    __half (*Bs)[128][HPAD] = (__half(*)[128][HPAD])(sh + 2 * 128 * HPAD);

    const int tid  = threadIdx.x;
    const int lane = tid & 31;
    const int warp = tid >> 5;
    const int wm   = warp & 3;
    const int wn   = warp >> 2;
    const int fr   = lane & 15;
    const int fk   = (lane >> 4) * 8;

    int sr[4], scol[4];
    const __half* agp[4];
    const __half* bgp[4];
    #pragma unroll
    for (int j = 0; j < 4; j++) {
        int chunk = tid + j * 256;
        sr[j] = chunk >> 3; scol[j] = (chunk & 7) * 8;
        agp[j] = aBase + (size_t)sr[j] * lda + scol[j];
        bgp[j] = bBase + (size_t)sr[j] * ldb + scol[j];
    }

    #pragma unroll
    for (int j = 0; j < 4; j++) {
        cp16(&As[0][sr[j]][scol[j]], agp[j]);
        cp16(&Bs[0][sr[j]][scol[j]], bgp[j]);
    }
    CP_COMMIT();
    CP_WAIT0();
    __syncthreads();

    const int NK = EMBED / 64;
    for (int it = 0; it < NK; it++) {
        const int buf = it & 1;
        if (it + 1 < NK) {
            const int kc = (it + 1) * 64;
            #pragma unroll
            for (int j = 0; j < 4; j++) {
                cp16(&As[buf ^ 1][sr[j]][scol[j]], agp[j] + kc);
                cp16(&Bs[buf ^ 1][sr[j]][scol[j]], bgp[j] + kc);
            }
            CP_COMMIT();
        }

        #pragma unroll
        for (int ks = 0; ks < 4; ks++) {
            const int k0 = ks * 16 + fk;
            uint32_t a[2][4], b[4][4];
            #pragma unroll
            for (int mi = 0; mi < 2; mi++)
                ldsm4(a[mi], &As[buf][wm * 32 + mi * 16 + fr][k0]);
            #pragma unroll
            for (int np = 0; np < 4; np++)
                ldsm4(b[np], &Bs[buf][wn * 64 + np * 16 + fr][k0]);
            #pragma unroll
            for (int np = 0; np < 4; np++) {
                #pragma unroll
                for (int mi = 0; mi < 2; mi++) {
                    mma16(acc.c[mi][2 * np    ], a[mi][0], a[mi][1], a[mi][2], a[mi][3],
                          b[np][0], b[np][2]);
                    mma16(acc.c[mi][2 * np + 1], a[mi][0], a[mi][1], a[mi][2], a[mi][3],
                          b[np][1], b[np][3]);
                }
            }
        }

        if (it + 1 < NK) CP_WAIT0();
        __syncthreads();
    }
}

// ============================================================================
// Kernel 1: QKV GEMM (fp16) -> fp16 Q/K [B,H,S,D] (Q scaled), V [B,H,D,S].
// ============================================================================
__global__ __launch_bounds__(256, 2) void qkv_kernel()
{
    const int n0 = blockIdx.x * 128;
    const int m0 = blockIdx.y * 128;

    GemmAcc acc;
    #pragma unroll
    for (int mi = 0; mi < 2; mi++)
        #pragma unroll
        for (int ni = 0; ni < 8; ni++)
            #pragma unroll
            for (int e = 0; e < 4; e++) acc.c[mi][ni][e] = 0.0f;

    gemm128h(acc, g_xh + (size_t)m0 * EMBED, g_wqkvh + (size_t)n0 * EMBED,
             EMBED, EMBED);

    const int lane = threadIdx.x & 31;
    const int warp = threadIdx.x >> 5;
    const int g    = lane >> 2;
    const int t4   = lane & 3;
    const int wm   = warp & 3;
    const int wn   = warp >> 2;

    const int mat = n0 >> 10;
    const int b   = m0 >> 11;
    const int s0l = m0 & 2047;
    const int h   = ((n0 & 1023) >> 6) + wn;
    const size_t bhOff = (size_t)(b * NHEADS + h);

    if (mat < 2) {
        __half* dst = ((mat == 0) ? g_qh : g_kh) + bhOff * SEQ * HEAD;
        const float scale = (mat == 0) ? 0.125f : 1.0f;
        #pragma unroll
        for (int mi = 0; mi < 2; mi++) {
            int s0r = s0l + wm * 32 + mi * 16 + g;
            #pragma unroll
            for (int ni = 0; ni < 8; ni++) {
                int d = ni * 8 + t4 * 2;
                *(__half2*)(dst + (size_t)(s0r    ) * HEAD + d) =
                    __floats2half2_rn(acc.c[mi][ni][0] * scale, acc.c[mi][ni][1] * scale);
                *(__half2*)(dst + (size_t)(s0r + 8) * HEAD + d) =
                    __floats2half2_rn(acc.c[mi][ni][2] * scale, acc.c[mi][ni][3] * scale);
            }
        }
    } else {
        // V transposed: dst[d][s]
        __half* dst = g_vh + bhOff * HEAD * SEQ;
        #pragma unroll
        for (int mi = 0; mi < 2; mi++) {
            int s0r = s0l + wm * 32 + mi * 16 + g;
            #pragma unroll
            for (int ni = 0; ni < 8; ni++) {
                int d = ni * 8 + t4 * 2;
                dst[(size_t)(d    ) * SEQ + s0r    ] = __float2half_rn(acc.c[mi][ni][0]);
                dst[(size_t)(d + 1) * SEQ + s0r    ] = __float2half_rn(acc.c[mi][ni][1]);
                dst[(size_t)(d    ) * SEQ + s0r + 8] = __float2half_rn(acc.c[mi][ni][2]);
                dst[(size_t)(d + 1) * SEQ + s0r + 8] = __float2half_rn(acc.c[mi][ni][3]);
            }
        }
    }
}

// ============================================================================
// Kernel 2: causal flash attention, full fp16 mma (m16n8k16).
// BM=128 (8 warps x 16 rows), BN=32 keys, D=64.  3-stage cp.async K/V ring.
// P stays in registers (accum layout -> A-fragment is thread-local).
// ============================================================================
__global__ __launch_bounds__(256, 2) void attn_kernel()
{
    extern __shared__ __half sh[];
    __half (*Qs)[72]     = (__half(*)[72])sh;                         // 128 x 72
    __half (*Ks)[32][72] = (__half(*)[32][72])(sh + 128 * 72);        // 3 x 32 x 72
    __half (*Vs)[64][40] = (__half(*)[64][40])(sh + 128 * 72 + 3 * 32 * 72); // 3 x 64 x 40

    const int bh = blockIdx.y;
    const int b  = bh >> 4;
    const int h  = bh & 15;
    const int qt = blockIdx.x;
    const int q0 = qt * 128;

    const int tid  = threadIdx.x;
    const int lane = tid & 31;
    const int warp = tid >> 5;
    const int g    = lane >> 2;
    const int t4   = lane & 3;
    const int fr   = lane & 15;
    const int fk   = (lane >> 4) * 8;

    const __half* qp = g_qh + ((size_t)bh * SEQ + q0) * HEAD;
    const __half* kp = g_kh + (size_t)bh * SEQ * HEAD;
    const __half* vp = g_vh + (size_t)bh * HEAD * SEQ;

    // ---- stage Q (fp16, pre-scaled), build 4 a-frags (d: 4 x 16) ----
    {
        #pragma unroll
        for (int j = 0; j < 4; j++) {
            int chunk = tid + j * 256;
            int r = chunk >> 3, c = (chunk & 7) * 8;
            cp16(&Qs[r][c], qp + (size_t)r * HEAD + c);
        }
        CP_COMMIT();
        CP_WAIT0();
        __syncthreads();
    }
    uint32_t qa[4][4];
    #pragma unroll
    for (int kf = 0; kf < 4; kf++)
        ldsm4(qa[kf], &Qs[warp * 16 + fr][kf * 16 + fk]);

    float o[8][4];
    #pragma unroll
    for (int dn = 0; dn < 8; dn++)
        #pragma unroll
        for (int e = 0; e < 4; e++) o[dn][e] = 0.0f;

    float m0 = -1e30f, m1 = -1e30f, l0 = 0.0f, l1 = 0.0f;

    const int nkt   = (qt + 1) * 4;
    const int row0b = q0 + warp * 16;
    const int qmaxw = row0b + 15;

    // K staging: 32 rows x 64 halves = 256 chunks (1/thread)
    const int kr = tid >> 3, kc = (tid & 7) * 8;
    // V staging: 64 rows(d) x 32 halves = 256 chunks (1/thread)
    const int vr = tid >> 2, vc = (tid & 3) * 8;

    #pragma unroll
    for (int st = 0; st < 2; st++) {
        const int k0 = st * 32;
        cp16(&Ks[st][kr][kc], kp + (size_t)(k0 + kr) * HEAD + kc);
        cp16(&Vs[st][vr][vc], vp + (size_t)vr * SEQ + k0 + vc);
        CP_COMMIT();
    }

    int sc = 0;
    for (int kt = 0; kt < nkt; kt++) {
        const int k0 = kt * 32;

        CP_WAIT1();
        __syncthreads();

        if (kt + 2 < nkt) {
            int sp = sc + 2; if (sp >= 3) sp -= 3;
            const int kn = k0 + 64;
            cp16(&Ks[sp][kr][kc], kp + (size_t)(kn + kr) * HEAD + kc);
            cp16(&Vs[sp][vr][vc], vp + (size_t)vr * SEQ + kn + vc);
            CP_COMMIT();
        }

        if (k0 <= qmaxw) {
            // ---- S = Q K^T : 4 kf x 2 np -> s[4][4] ----
            float s[4][4];
            #pragma unroll
            for (int nf = 0; nf < 4; nf++)
                #pragma unroll
                for (int e = 0; e < 4; e++) s[nf][e] = 0.0f;

            #pragma unroll
            for (int kf = 0; kf < 4; kf++) {
                #pragma unroll
                for (int np = 0; np < 2; np++) {
                    uint32_t bfr[4];
                    ldsm4(bfr, &Ks[sc][np * 16 + fr][kf * 16 + fk]);
                    mma16(s[2 * np    ], qa[kf][0], qa[kf][1], qa[kf][2], qa[kf][3],
                          bfr[0], bfr[2]);
                    mma16(s[2 * np + 1], qa[kf][0], qa[kf][1], qa[kf][2], qa[kf][3],
                          bfr[1], bfr[3]);
                }
            }

            // ---- causal mask ----
            const int r0 = row0b + g;
            const int r1 = r0 + 8;
            #pragma unroll
            for (int nf = 0; nf < 4; nf++) {
                int col0 = k0 + nf * 8 + t4 * 2;
                if (col0     > r0) s[nf][0] = -1e30f;
                if (col0 + 1 > r0) s[nf][1] = -1e30f;
                if (col0     > r1) s[nf][2] = -1e30f;
                if (col0 + 1 > r1) s[nf][3] = -1e30f;
            }

            // ---- online softmax (fp32, in registers) ----
            float rm0 = -1e30f, rm1 = -1e30f;
            #pragma unroll
            for (int nf = 0; nf < 4; nf++) {
                rm0 = fmaxf(rm0, fmaxf(s[nf][0], s[nf][1]));
                rm1 = fmaxf(rm1, fmaxf(s[nf][2], s[nf][3]));
            }
            rm0 = fmaxf(rm0, __shfl_xor_sync(0xffffffffu, rm0, 1));
            rm0 = fmaxf(rm0, __shfl_xor_sync(0xffffffffu, rm0, 2));
            rm1 = fmaxf(rm1, __shfl_xor_sync(0xffffffffu, rm1, 1));
            rm1 = fmaxf(rm1, __shfl_xor_sync(0xffffffffu, rm1, 2));

            float nm0 = fmaxf(m0, rm0), nm1 = fmaxf(m1, rm1);
            float sc0 = __expf(m0 - nm0), sc1 = __expf(m1 - nm1);

            float sum0 = 0.0f, sum1 = 0.0f;
            #pragma unroll
            for (int nf = 0; nf < 4; nf++) {
                s[nf][0] = __expf(s[nf][0] - nm0);
                s[nf][1] = __expf(s[nf][1] - nm0);
                s[nf][2] = __expf(s[nf][2] - nm1);
                s[nf][3] = __expf(s[nf][3] - nm1);
                sum0 += s[nf][0] + s[nf][1];
                sum1 += s[nf][2] + s[nf][3];
            }
            sum0 += __shfl_xor_sync(0xffffffffu, sum0, 1);
            sum0 += __shfl_xor_sync(0xffffffffu, sum0, 2);
            sum1 += __shfl_xor_sync(0xffffffffu, sum1, 1);
            sum1 += __shfl_xor_sync(0xffffffffu, sum1, 2);

            l0 = l0 * sc0 + sum0;  m0 = nm0;
            l1 = l1 * sc1 + sum1;  m1 = nm1;

            #pragma unroll
            for (int dn = 0; dn < 8; dn++) {
                o[dn][0] *= sc0; o[dn][1] *= sc0;
                o[dn][2] *= sc1; o[dn][3] *= sc1;
            }

            // ---- O += P V : P packed thread-locally into A-frags ----
            #pragma unroll
            for (int kf = 0; kf < 2; kf++) {
                uint32_t pa0 = h2u(__floats2half2_rn(s[2 * kf    ][0], s[2 * kf    ][1]));
                uint32_t pa1 = h2u(__floats2half2_rn(s[2 * kf    ][2], s[2 * kf    ][3]));
                uint32_t pa2 = h2u(__floats2half2_rn(s[2 * kf + 1][0], s[2 * kf + 1][1]));
                uint32_t pa3 = h2u(__floats2half2_rn(s[2 * kf + 1][2], s[2 * kf + 1][3]));
                #pragma unroll
                for (int np = 0; np < 4; np++) {
                    uint32_t bfr[4];
                    ldsm4(bfr, &Vs[sc][np * 16 + fr][kf * 16 + fk]);
                    mma16(o[2 * np    ], pa0, pa1, pa2, pa3, bfr[0], bfr[2]);
                    mma16(o[2 * np + 1], pa0, pa1, pa2, pa3, bfr[1], bfr[3]);
                }
            }
        }

        if (++sc == 3) sc = 0;
    }

    // ---- epilogue: normalize, write fp16 [B,S,H,D] ----
    const float inv0 = 1.0f / l0;
    const float inv1 = 1.0f / l1;
    const int r0 = q0 + warp * 16 + g;
    __half* ob = g_attnh + (size_t)b * SEQ * EMBED + (size_t)h * HEAD;
    #pragma unroll
    for (int dn = 0; dn < 8; dn++) {
        int d = dn * 8 + t4 * 2;
        *(__half2*)(ob + (size_t)(r0    ) * EMBED + d) =
            __floats2half2_rn(o[dn][0] * inv0, o[dn][1] * inv0);
        *(__half2*)(ob + (size_t)(r0 + 8) * EMBED + d) =
            __floats2half2_rn(o[dn][2] * inv1, o[dn][3] * inv1);
    }
}

// ============================================================================
// Kernel 3: output projection (fp16, R11 proven).
// ============================================================================
__global__ __launch_bounds__(256, 2) void proj_kernel(
    const float* __restrict__ bo,
    float* __restrict__ out)
{
    const int e0 = blockIdx.x * 128;
    const int m0 = blockIdx.y * 128;

    GemmAcc acc;
    #pragma unroll
    for (int mi = 0; mi < 2; mi++)
        #pragma unroll
        for (int ni = 0; ni < 8; ni++)
            #pragma unroll
            for (int e = 0; e < 4; e++) acc.c[mi][ni][e] = 0.0f;

    gemm128h(acc, g_attnh + (size_t)m0 * EMBED, g_woh + (size_t)e0 * EMBED,
             EMBED, EMBED);

    const int lane = threadIdx.x & 31;
    const int warp = threadIdx.x >> 5;
    const int g    = lane >> 2;
    const int t4   = lane & 3;
    const int wm   = warp & 3;
    const int wn   = warp >> 2;

    #pragma unroll
    for (int mi = 0; mi < 2; mi++) {
        int r0 = m0 + wm * 32 + mi * 16 + g;
        #pragma unroll
        for (int ni = 0; ni < 8; ni++) {
            int e = e0 + wn * 64 + ni * 8 + t4 * 2;
            out[(size_t)(r0    ) * EMBED + e    ] = acc.c[mi][ni][0] + bo[e];
            out[(size_t)(r0    ) * EMBED + e + 1] = acc.c[mi][ni][1] + bo[e + 1];
            out[(size_t)(r0 + 8) * EMBED + e    ] = acc.c[mi][ni][2] + bo[e];
            out[(size_t)(r0 + 8) * EMBED + e + 1] = acc.c[mi][ni][3] + bo[e + 1];
        }
    }
}

// ============================================================================
extern "C" void kernel_launch(void* const* d_in, const int* in_sizes, int n_in,
                              void* d_out, int out_size)
{
    const float* x  = (const float*)d_in[0];
    const float* Wq = (const float*)d_in[1];
    const float* Wk = (const float*)d_in[2];
    const float* Wv = (const float*)d_in[3];
    const float* Wo = (const float*)d_in[4];
    const float* bo = (const float*)d_in[5];
    float* out = (float*)d_out;

    (void)in_sizes; (void)n_in; (void)out_size;

    cudaFuncSetAttribute(qkv_kernel,  cudaFuncAttributeMaxDynamicSharedMemorySize, GEMM_SMEM);
    cudaFuncSetAttribute(attn_kernel, cudaFuncAttributeMaxDynamicSharedMemorySize, ATTN_SMEM);
    cudaFuncSetAttribute(proj_kernel, cudaFuncAttributeMaxDynamicSharedMemorySize, GEMM_SMEM);

    x2h_kernel<<<NTOK * EMBED / 1024, 256>>>(x);
    packw_kernel<<<QKVN * EMBED / 256, 256>>>(Wq, Wk, Wv);
    wo2h_kernel<<<EMBED * EMBED / 1024, 256>>>(Wo);

    qkv_kernel<<<dim3(QKVN / 128, NTOK / 128), 256, GEMM_SMEM>>>();
    attn_kernel<<<dim3(SEQ / 128, BATCH * NHEADS), 256, ATTN_SMEM>>>();
    proj_kernel<<<dim3(EMBED / 128, NTOK / 128), 256, GEMM_SMEM>>>(bo, out);
}